// round 11
// baseline (speedup 1.0000x reference)
#include <cuda_runtime.h>
#include <cuda_bf16.h>
#include <cstdint>
#include <math.h>

#define Bb 128
#define Tt 1024
#define Nn 256
#define Mm 256
#define Gg 768
#define ROWS (Bb*Tt)

// Scratch (allocation-free rule: __device__ globals)
__device__ float g_gx[(size_t)ROWS * Gg];    // input-gate activations
__device__ float g_out0[(size_t)ROWS * Mm];  // layer-0 output

typedef unsigned long long u64t;

// ---------------- packed f32x2 helpers ----------------
__device__ __forceinline__ u64t ffma2(u64t a, u64t b, u64t c) {
    u64t d;
    asm("fma.rn.f32x2 %0, %1, %2, %3;" : "=l"(d) : "l"(a), "l"(b), "l"(c));
    return d;
}
__device__ __forceinline__ float2 unpack2(u64t v) {
    float2 r; asm("mov.b64 {%0, %1}, %2;" : "=f"(r.x), "=f"(r.y) : "l"(v)); return r;
}

// ---------------- cluster / DSMEM helpers ----------------
__device__ __forceinline__ uint32_t smem_u32(const void* p) {
    uint32_t a;
    asm("{ .reg .u64 t; cvta.to.shared.u64 t, %1; cvt.u32.u64 %0, t; }" : "=r"(a) : "l"(p));
    return a;
}
__device__ __forceinline__ uint32_t cl_rank() {
    uint32_t r; asm("mov.u32 %0, %%cluster_ctarank;" : "=r"(r)); return r;
}
__device__ __forceinline__ uint32_t cl_map(uint32_t addr, uint32_t rank) {
    uint32_t r; asm("mapa.shared::cluster.u32 %0, %1, %2;" : "=r"(r) : "r"(addr), "r"(rank)); return r;
}
__device__ __forceinline__ void st_cl_f32(uint32_t addr, float v) {
    asm volatile("st.shared::cluster.f32 [%0], %1;" :: "r"(addr), "f"(v) : "memory");
}
__device__ __forceinline__ void cl_sync() {
    asm volatile("barrier.cluster.arrive.aligned;" ::: "memory");
    asm volatile("barrier.cluster.wait.aligned;" ::: "memory");
}

// ---------------- mbarrier helpers ----------------
__device__ __forceinline__ void mbar_init(uint32_t a, uint32_t cnt) {
    asm volatile("mbarrier.init.shared.b64 [%0], %1;" :: "r"(a), "r"(cnt) : "memory");
}
__device__ __forceinline__ void mbar_arrive_cluster(uint32_t local_addr, uint32_t pr) {
    asm volatile(
        "{\n\t.reg .b32 ra;\n\t"
        "mapa.shared::cluster.u32 ra, %0, %1;\n\t"
        "mbarrier.arrive.release.cluster.shared::cluster.b64 _, [ra];\n\t}"
        :: "r"(local_addr), "r"(pr) : "memory");
}
__device__ __forceinline__ void mbar_wait_parity_cluster(uint32_t a, uint32_t parity) {
    asm volatile(
        "{\n\t.reg .pred P1;\n\t"
        "WL_%=:\n\t"
        "mbarrier.try_wait.parity.acquire.cluster.shared::cta.b64 P1, [%0], %1, 0x989680;\n\t"
        "@P1 bra.uni WD_%=;\n\t"
        "bra.uni WL_%=;\n\t"
        "WD_%=:\n\t}"
        :: "r"(a), "r"(parity) : "memory");
}

__device__ __forceinline__ float fast_sigmoid(float x) {
    return 1.f / (1.f + __expf(-x));
}
__device__ __forceinline__ float fast_tanh(float x) {
    return 1.f - __fdividef(2.f, 1.f + __expf(2.f * x));
}
__device__ __forceinline__ bool elect1() {
    uint32_t p;
    asm volatile("{\n\t.reg .pred p;\n\telect.sync _|p, 0xFFFFFFFF;\n\tselp.b32 %0,1,0,p;\n\t}" : "=r"(p));
    return p != 0;
}

// ---------------- warp-MMA helpers (baseline ISA, no tcgen05) ----------------
__device__ __forceinline__ void ldsm4(uint32_t r[4], uint32_t addr) {
    asm volatile("ldmatrix.sync.aligned.m8n8.x4.shared.b16 {%0,%1,%2,%3}, [%4];"
                 : "=r"(r[0]), "=r"(r[1]), "=r"(r[2]), "=r"(r[3]) : "r"(addr));
}
__device__ __forceinline__ void hmma(float4& d, const uint32_t a[4], const uint32_t* b) {
    asm volatile("mma.sync.aligned.m16n8k16.row.col.f32.bf16.bf16.f32 "
                 "{%0,%1,%2,%3}, {%4,%5,%6,%7}, {%8,%9}, {%0,%1,%2,%3};"
                 : "+f"(d.x), "+f"(d.y), "+f"(d.z), "+f"(d.w)
                 : "r"(a[0]), "r"(a[1]), "r"(a[2]), "r"(a[3]), "r"(b[0]), "r"(b[1]));
}

// split fp32 -> bf16 hi + bf16 residual, pack pairs into u32
__device__ __forceinline__ void split2(float x, float y, uint32_t& hi, uint32_t& lo) {
    __nv_bfloat16 hx = __float2bfloat16(x);
    __nv_bfloat16 hy = __float2bfloat16(y);
    __nv_bfloat16 lx = __float2bfloat16(x - __bfloat162float(hx));
    __nv_bfloat16 ly = __float2bfloat16(y - __bfloat162float(hy));
    hi = (uint32_t)*(uint16_t*)&hx | ((uint32_t)*(uint16_t*)&hy << 16);
    lo = (uint32_t)*(uint16_t*)&lx | ((uint32_t)*(uint16_t*)&ly << 16);
}

// ---------------- input-gate GEMM via mma.sync bf16x3 (fp32-accurate) ----------------
#define SW_HI   0
#define SW_LO   33792
#define SA_HI   67584
#define SA_LO   73728
#define SBIAS   79872
#define SM_GEMM 80128
#define WSTRIDE 528   // bytes per gate row (256 bf16 + 8 pad)

__global__ __launch_bounds__(256, 2) void gemm_hmma(
    const float* __restrict__ A, const float* __restrict__ W,
    const float* __restrict__ bias, float* __restrict__ C)
{
    extern __shared__ char sm[];
    const uint32_t sb = smem_u32(sm);
    const int tid  = threadIdx.x;
    const int lane = tid & 31, warp = tid >> 5;
    const int wm = warp >> 1, wn = warp & 1;
    const int g0 = blockIdx.x * 64;

    // one-time: W tile fp32 -> bf16 hi/lo SMEM
    {
        const int r = tid >> 2, kq = tid & 3;
        const float4* wp = (const float4*)(W + (size_t)(g0 + r) * 256 + kq * 64);
        char* dh = sm + SW_HI + r * WSTRIDE + kq * 128;
        char* dl = sm + SW_LO + r * WSTRIDE + kq * 128;
#pragma unroll
        for (int kk = 0; kk < 16; ++kk) {
            float4 v = wp[kk];
            uint2 h, l;
            split2(v.x, v.y, h.x, l.x);
            split2(v.z, v.w, h.y, l.y);
            *(uint2*)(dh + kk * 8) = h;
            *(uint2*)(dl + kk * 8) = l;
        }
    }
    if (tid < 64) ((float*)(sm + SBIAS))[tid] = bias[g0 + tid];

    const int lq = lane >> 3, l8 = lane & 7;
    const uint32_t arow = (uint32_t)((lq & 1) * 8 + l8);
    const uint32_t akh  = (uint32_t)((lq >> 1) * 16);
    const uint32_t bgat = (uint32_t)((lq >> 1) * 8 + l8);
    const uint32_t bkh  = (uint32_t)((lq & 1) * 8);
    const int grp = lane >> 2, tig = lane & 3;

    __syncthreads();

    for (int rt = blockIdx.y; rt < 1024; rt += 24) {
        const float* Ab = A + (size_t)rt * 128 * 256;
        const int prow = tid >> 1, phalf = tid & 1;

        float4 pa0, pa1;
        {
            const float4* ap = (const float4*)(Ab + (size_t)prow * 256 + phalf * 8);
            pa0 = ap[0]; pa1 = ap[1];
        }

        float4 d[2][4];
#pragma unroll
        for (int i = 0; i < 2; ++i)
#pragma unroll
            for (int j = 0; j < 4; ++j) d[i][j] = float4{0.f, 0.f, 0.f, 0.f};

        for (int ks = 0; ks < 16; ++ks) {
            __syncthreads();
            {
                uint4 h, l;
                split2(pa0.x, pa0.y, h.x, l.x);
                split2(pa0.z, pa0.w, h.y, l.y);
                split2(pa1.x, pa1.y, h.z, l.z);
                split2(pa1.z, pa1.w, h.w, l.w);
                *(uint4*)(sm + SA_HI + prow * 48 + phalf * 16) = h;
                *(uint4*)(sm + SA_LO + prow * 48 + phalf * 16) = l;
            }
            __syncthreads();
            if (ks + 1 < 16) {
                const float4* ap = (const float4*)(Ab + (size_t)prow * 256 + (ks + 1) * 16 + phalf * 8);
                pa0 = ap[0]; pa1 = ap[1];
            }

            uint32_t ah[2][4], al[2][4], bhr[2][4], blr[2][4];
#pragma unroll
            for (int mf = 0; mf < 2; ++mf) {
                uint32_t off = (uint32_t)((wm * 32 + mf * 16 + arow) * 48) + akh;
                ldsm4(ah[mf], sb + SA_HI + off);
                ldsm4(al[mf], sb + SA_LO + off);
            }
#pragma unroll
            for (int bp = 0; bp < 2; ++bp) {
                uint32_t off = (uint32_t)((wn * 32 + bp * 16 + bgat) * WSTRIDE)
                             + (uint32_t)((ks * 16 + bkh) * 2);
                ldsm4(bhr[bp], sb + SW_HI + off);
                ldsm4(blr[bp], sb + SW_LO + off);
            }
#pragma unroll
            for (int mf = 0; mf < 2; ++mf)
#pragma unroll
                for (int nf = 0; nf < 4; ++nf) {
                    const uint32_t* bh = &bhr[nf >> 1][(nf & 1) * 2];
                    const uint32_t* bl = &blr[nf >> 1][(nf & 1) * 2];
                    hmma(d[mf][nf], ah[mf], bh);
                    hmma(d[mf][nf], ah[mf], bl);
                    hmma(d[mf][nf], al[mf], bh);
                }
        }

        const float* bs = (const float*)(sm + SBIAS);
#pragma unroll
        for (int mf = 0; mf < 2; ++mf) {
            size_t row = (size_t)rt * 128 + wm * 32 + mf * 16 + grp;
#pragma unroll
            for (int nf = 0; nf < 4; ++nf) {
                int gc = wn * 32 + nf * 8 + 2 * tig;
                float bx = bs[gc], by = bs[gc + 1];
                float4 v = d[mf][nf];
                *(float2*)(C + row * 768 + g0 + gc)       = float2{v.x + bx, v.y + by};
                *(float2*)(C + (row + 8) * 768 + g0 + gc) = float2{v.z + bx, v.w + by};
            }
        }
    }
}

// ---------------- GRU recurrence v3: full-reg r/z weights, 256 threads ----------------
// Cluster of 4 CTAs owns 4 batch rows; CTA rank owns h columns [rank*64, +64).
// Thread (c 0..63, q 0..3): all 3 gates x 4 rows for column c, k-quarter q.
//   r,z gate weights: 128 REGISTERS per thread (no LDS).  n gate: SMEM (64KB).
// Per-source mbarrier slots: slot s on every CTA is armed by CTA s's 8 warps
// (elected release-arrive per warp). Warp-group q waits only slot q -> per-source
// pipelining of the DSMEM h broadcast. ONE __syncthreads per step; sGh and the
// epilogue are parity-double-buffered so the next dot can't clobber laggards.
#define RSM_WN   0        // n-gate weights: [q(4)][kk(16)][c(64)] float4 = 16384 floats
#define RSM_H    16384    // h double buffer: [2][4 rows][256] = 2048 floats
#define RSM_GH   18432    // gh partials: [2 parity][4 q][3 g][4 r][64 c] = 6144 floats
#define RSM_MBAR 24576    // 4 mbarrier slots (8B each)
#define REC_SMEM (24576*4 + 64)

__global__ __launch_bounds__(256, 1) __cluster_dims__(4, 1, 1)
void gru_rec(const float* __restrict__ gx, const float* __restrict__ Whh,
             const float* __restrict__ bhh, float* __restrict__ out,
             float* __restrict__ hid)
{
    extern __shared__ float smem[];
    float4* sWn4 = (float4*)smem;             // n-gate weights
    float*  sH   = smem + RSM_H;
    float*  sGh  = smem + RSM_GH;
    const uint32_t mbar0 = smem_u32(smem) + RSM_MBAR * 4;

    const uint32_t rank = cl_rank();
    const int b0  = (blockIdx.x >> 2) * 4;
    const int tid = threadIdx.x;
    const int q   = tid >> 6;          // k-quarter, warp-uniform (2 warps per q)
    const int c   = tid & 63;          // column within chunk

    if (tid == 0)
        for (int s = 0; s < 4; ++s) mbar_init(mbar0 + s * 8, 8);

    // n-gate weights -> SMEM [q][kk][c] float4
    for (int idx = tid; idx < 4096; idx += 256) {
        int qq = idx >> 10, kk = (idx >> 6) & 15, j = idx & 63;
        sWn4[idx] = ((const float4*)Whh)[(size_t)(512 + rank * 64 + j) * 64 + qq * 16 + kk];
    }
    for (int i = tid; i < 2048; i += 256) sH[i] = 0.f;

    // r,z gate weights -> registers (32+32 u64 = 128 regs)
    u64t wrR[32], wrZ[32];
    {
        const float* wbR = Whh + (size_t)(rank * 64 + c) * 256 + q * 64;
        const float* wbZ = wbR + 256 * 256;
#pragma unroll
        for (int kk = 0; kk < 16; ++kk) {
            ulonglong2 a = *(const ulonglong2*)(wbR + kk * 4);
            ulonglong2 b = *(const ulonglong2*)(wbZ + kk * 4);
            wrR[2 * kk] = a.x; wrR[2 * kk + 1] = a.y;
            wrZ[2 * kk] = b.x; wrZ[2 * kk + 1] = b.y;
        }
    }

    // epilogue constants: this thread handles (row = q, col = rank*64+c)
    const float bR = bhh[rank * 64 + c];
    const float bZ = bhh[256 + rank * 64 + c];
    const float bN = bhh[512 + rank * 64 + c];
    const size_t gxBase  = ((size_t)(b0 + q) * 1024) * 768 + rank * 64 + c;
    const size_t outBase = ((size_t)(b0 + q) * 1024) * 256 + rank * 64 + c;

    float gxr = gx[gxBase];
    float gxz = gx[gxBase + 256];
    float gxn = gx[gxBase + 512];

    cl_sync();  // smem weights, zeroed h, mbarrier inits visible cluster-wide

    const uint32_t myslot = mbar0 + (uint32_t)q * 8;

    for (int t = 0; t < 1024; ++t) {
        // h chunk q (cols q*64..q*64+63) of step t is produced by CTA q at the
        // end of step t-1; wait for CTA q's 8 warp-arrives (phase t-1).
        if (t > 0)
            mbar_wait_parity_cluster(myslot, (uint32_t)((t - 1) & 1));

        // ---- dot: 3 gates x 4 rows x 64 k (quarter q), col c ----
        {
            const float* hb = sH + (t & 1) * 1024 + q * 64;
            const float4* wn = sWn4 + q * 1024 + c;
            u64t acc[12];
#pragma unroll
            for (int i = 0; i < 12; ++i) acc[i] = 0ull;
#pragma unroll
            for (int kk = 0; kk < 16; ++kk) {
                ulonglong2 wnv = *(const ulonglong2*)(wn + kk * 64);
                u64t wrx = wrR[2 * kk], wry = wrR[2 * kk + 1];
                u64t wzx = wrZ[2 * kk], wzy = wrZ[2 * kk + 1];
#pragma unroll
                for (int r = 0; r < 4; ++r) {
                    ulonglong2 hv = *(const ulonglong2*)(hb + r * 256 + kk * 4);
                    acc[r]     = ffma2(wrx, hv.x, acc[r]);
                    acc[r]     = ffma2(wry, hv.y, acc[r]);
                    acc[4 + r] = ffma2(wzx, hv.x, acc[4 + r]);
                    acc[4 + r] = ffma2(wzy, hv.y, acc[4 + r]);
                    acc[8 + r] = ffma2(wnv.x, hv.x, acc[8 + r]);
                    acc[8 + r] = ffma2(wnv.y, hv.y, acc[8 + r]);
                }
            }
            float* sg = sGh + (t & 1) * 3072 + q * 768 + c;
#pragma unroll
            for (int i = 0; i < 12; ++i) {
                float2 p = unpack2(acc[i]);
                sg[i * 64] = p.x + p.y;
            }
        }
        __syncthreads();

        // ---- epilogue: same 256 threads, row = q ----
        {
            const float* sg2 = sGh + (t & 1) * 3072;
            const int base = q * 64 + c;     // [g][r=q][c] offset: g*256 + q*64 + c
            float ghr = 0.f, ghz = 0.f, ghn = 0.f;
#pragma unroll
            for (int qq = 0; qq < 4; ++qq) {
                ghr += sg2[qq * 768 + base];
                ghz += sg2[qq * 768 + 256 + base];
                ghn += sg2[qq * 768 + 512 + base];
            }
            float rg = fast_sigmoid(gxr + ghr + bR);
            float zg = fast_sigmoid(gxz + ghz + bZ);
            float hp = sH[(t & 1) * 1024 + q * 256 + rank * 64 + c];
            float n  = fast_tanh(fmaf(rg, ghn + bN, gxn));
            float hnew = fmaf(zg, hp - n, n);   // (1-z)*n + z*hp

            float* hdst = sH + ((t + 1) & 1) * 1024 + q * 256 + rank * 64 + c;
            *hdst = hnew;
            uint32_t laddr = smem_u32(hdst);
#pragma unroll
            for (int pr = 0; pr < 4; ++pr)
                if (pr != (int)rank) st_cl_f32(cl_map(laddr, (uint32_t)pr), hnew);

            __syncwarp();
            if (elect1()) {
                asm volatile("fence.acq_rel.cluster;" ::: "memory");
                uint32_t slotR = mbar0 + rank * 8;   // slot indexed by SOURCE rank
#pragma unroll
                for (int pr = 0; pr < 4; ++pr) mbar_arrive_cluster(slotR, (uint32_t)pr);
            }

            // hidden under barrier latency: out store + next-step gx prefetch
            out[outBase + (size_t)t * 256] = hnew;
            if (t + 1 < 1024) {
                size_t gbase = gxBase + (size_t)(t + 1) * 768;
                gxr = gx[gbase];
                gxz = gx[gbase + 256];
                gxn = gx[gbase + 512];
            }
        }
    }

    __syncthreads();  // local chunk of final h complete CTA-wide
    hid[(size_t)(b0 + q) * 256 + rank * 64 + c] =
        sH[q * 256 + rank * 64 + c];            // final buffer = (1024 & 1) = 0
    cl_sync();  // no CTA exits while peers may still target its SMEM
}

// ---------------- launch ----------------
extern "C" void kernel_launch(void* const* d_in, const int* in_sizes, int n_in,
                              void* d_out, int out_size)
{
    const float* X      = (const float*)d_in[0];
    const float* w_ih_0 = (const float*)d_in[1];
    const float* w_hh_0 = (const float*)d_in[2];
    const float* b_ih_0 = (const float*)d_in[3];
    const float* b_hh_0 = (const float*)d_in[4];
    const float* w_ih_1 = (const float*)d_in[5];
    const float* w_hh_1 = (const float*)d_in[6];
    const float* b_ih_1 = (const float*)d_in[7];
    const float* b_hh_1 = (const float*)d_in[8];

    float* out1 = (float*)d_out;
    float* hid  = out1 + (size_t)ROWS * Mm;

    float *gx = nullptr, *o0 = nullptr;
    cudaGetSymbolAddress((void**)&gx, g_gx);
    cudaGetSymbolAddress((void**)&o0, g_out0);

    cudaFuncSetAttribute(gru_rec, cudaFuncAttributeMaxDynamicSharedMemorySize, REC_SMEM);
    cudaFuncSetAttribute(gemm_hmma, cudaFuncAttributeMaxDynamicSharedMemorySize, SM_GEMM);

    dim3 ggrid(12, 24);   // 12 gate-tiles x 24 row-streams

    // layer 0
    gemm_hmma<<<ggrid, 256, SM_GEMM>>>(X, w_ih_0, b_ih_0, gx);
    gru_rec<<<128, 256, REC_SMEM>>>(gx, w_hh_0, b_hh_0, o0, hid);
    // layer 1
    gemm_hmma<<<ggrid, 256, SM_GEMM>>>(o0, w_ih_1, b_ih_1, gx);
    gru_rec<<<128, 256, REC_SMEM>>>(gx, w_hh_1, b_hh_1, out1, hid + (size_t)Bb * Mm);
}

// round 12
// speedup vs baseline: 1.4185x; 1.4185x over previous
#include <cuda_runtime.h>
#include <cuda_bf16.h>
#include <cstdint>
#include <math.h>

#define Bb 128
#define Tt 1024
#define Nn 256
#define Mm 256
#define Gg 768
#define ROWS (Bb*Tt)

// Scratch (allocation-free rule: __device__ globals)
__device__ float g_gx[(size_t)ROWS * Gg];    // input-gate activations
__device__ float g_out0[(size_t)ROWS * Mm];  // layer-0 output

typedef unsigned long long u64t;

// ---------------- packed f32x2 helpers ----------------
__device__ __forceinline__ u64t ffma2(u64t a, u64t b, u64t c) {
    u64t d;
    asm("fma.rn.f32x2 %0, %1, %2, %3;" : "=l"(d) : "l"(a), "l"(b), "l"(c));
    return d;
}
__device__ __forceinline__ float2 unpack2(u64t v) {
    float2 r; asm("mov.b64 {%0, %1}, %2;" : "=f"(r.x), "=f"(r.y) : "l"(v)); return r;
}

// ---------------- cluster / DSMEM helpers ----------------
__device__ __forceinline__ uint32_t smem_u32(const void* p) {
    uint32_t a;
    asm("{ .reg .u64 t; cvta.to.shared.u64 t, %1; cvt.u32.u64 %0, t; }" : "=r"(a) : "l"(p));
    return a;
}
__device__ __forceinline__ uint32_t cl_rank() {
    uint32_t r; asm("mov.u32 %0, %%cluster_ctarank;" : "=r"(r)); return r;
}
__device__ __forceinline__ uint32_t cl_map(uint32_t addr, uint32_t rank) {
    uint32_t r; asm("mapa.shared::cluster.u32 %0, %1, %2;" : "=r"(r) : "r"(addr), "r"(rank)); return r;
}
__device__ __forceinline__ void st_cl_f32(uint32_t addr, float v) {
    asm volatile("st.shared::cluster.f32 [%0], %1;" :: "r"(addr), "f"(v) : "memory");
}
__device__ __forceinline__ void cl_sync() {
    asm volatile("barrier.cluster.arrive.aligned;" ::: "memory");
    asm volatile("barrier.cluster.wait.aligned;" ::: "memory");
}

// ---------------- mbarrier helpers ----------------
__device__ __forceinline__ void mbar_init(uint32_t a, uint32_t cnt) {
    asm volatile("mbarrier.init.shared.b64 [%0], %1;" :: "r"(a), "r"(cnt) : "memory");
}
__device__ __forceinline__ void mbar_arrive_cluster(uint32_t local_addr, uint32_t pr) {
    asm volatile(
        "{\n\t.reg .b32 ra;\n\t"
        "mapa.shared::cluster.u32 ra, %0, %1;\n\t"
        "mbarrier.arrive.release.cluster.shared::cluster.b64 _, [ra];\n\t}"
        :: "r"(local_addr), "r"(pr) : "memory");
}
__device__ __forceinline__ void mbar_wait_parity_cluster(uint32_t a, uint32_t parity) {
    asm volatile(
        "{\n\t.reg .pred P1;\n\t"
        "WL_%=:\n\t"
        "mbarrier.try_wait.parity.acquire.cluster.shared::cta.b64 P1, [%0], %1, 0x989680;\n\t"
        "@P1 bra.uni WD_%=;\n\t"
        "bra.uni WL_%=;\n\t"
        "WD_%=:\n\t}"
        :: "r"(a), "r"(parity) : "memory");
}

__device__ __forceinline__ float fast_sigmoid(float x) {
    return 1.f / (1.f + __expf(-x));
}
__device__ __forceinline__ float fast_tanh(float x) {
    return 1.f - __fdividef(2.f, 1.f + __expf(2.f * x));
}
__device__ __forceinline__ bool elect1() {
    uint32_t p;
    asm volatile("{\n\t.reg .pred p;\n\telect.sync _|p, 0xFFFFFFFF;\n\tselp.b32 %0,1,0,p;\n\t}" : "=r"(p));
    return p != 0;
}

// ---------------- warp-MMA helpers (baseline ISA, no tcgen05) ----------------
__device__ __forceinline__ void ldsm4(uint32_t r[4], uint32_t addr) {
    asm volatile("ldmatrix.sync.aligned.m8n8.x4.shared.b16 {%0,%1,%2,%3}, [%4];"
                 : "=r"(r[0]), "=r"(r[1]), "=r"(r[2]), "=r"(r[3]) : "r"(addr));
}
__device__ __forceinline__ void hmma(float4& d, const uint32_t a[4], const uint32_t* b) {
    asm volatile("mma.sync.aligned.m16n8k16.row.col.f32.bf16.bf16.f32 "
                 "{%0,%1,%2,%3}, {%4,%5,%6,%7}, {%8,%9}, {%0,%1,%2,%3};"
                 : "+f"(d.x), "+f"(d.y), "+f"(d.z), "+f"(d.w)
                 : "r"(a[0]), "r"(a[1]), "r"(a[2]), "r"(a[3]), "r"(b[0]), "r"(b[1]));
}

// split fp32 -> bf16 hi + bf16 residual, pack pairs into u32
__device__ __forceinline__ void split2(float x, float y, uint32_t& hi, uint32_t& lo) {
    __nv_bfloat16 hx = __float2bfloat16(x);
    __nv_bfloat16 hy = __float2bfloat16(y);
    __nv_bfloat16 lx = __float2bfloat16(x - __bfloat162float(hx));
    __nv_bfloat16 ly = __float2bfloat16(y - __bfloat162float(hy));
    hi = (uint32_t)*(uint16_t*)&hx | ((uint32_t)*(uint16_t*)&hy << 16);
    lo = (uint32_t)*(uint16_t*)&lx | ((uint32_t)*(uint16_t*)&ly << 16);
}

// ---------------- input-gate GEMM via mma.sync bf16x3 (fp32-accurate) ----------------
// Double-buffered A staging: ONE __syncthreads per k-step.
#define SW_HI   0
#define SW_LO   33792
#define SA_HI   67584     // + bufsel*12288
#define SA_LO   73728     // = SA_HI + 6144
#define SBIAS   92160
#define SM_GEMM 92416
#define WSTRIDE 528   // bytes per gate row (256 bf16 + 8 pad)

__global__ __launch_bounds__(256, 2) void gemm_hmma(
    const float* __restrict__ A, const float* __restrict__ W,
    const float* __restrict__ bias, float* __restrict__ C)
{
    extern __shared__ char sm[];
    const uint32_t sb = smem_u32(sm);
    const int tid  = threadIdx.x;
    const int lane = tid & 31, warp = tid >> 5;
    const int wm = warp >> 1, wn = warp & 1;
    const int g0 = blockIdx.x * 64;

    // one-time: W tile fp32 -> bf16 hi/lo SMEM
    {
        const int r = tid >> 2, kq = tid & 3;
        const float4* wp = (const float4*)(W + (size_t)(g0 + r) * 256 + kq * 64);
        char* dh = sm + SW_HI + r * WSTRIDE + kq * 128;
        char* dl = sm + SW_LO + r * WSTRIDE + kq * 128;
#pragma unroll
        for (int kk = 0; kk < 16; ++kk) {
            float4 v = wp[kk];
            uint2 h, l;
            split2(v.x, v.y, h.x, l.x);
            split2(v.z, v.w, h.y, l.y);
            *(uint2*)(dh + kk * 8) = h;
            *(uint2*)(dl + kk * 8) = l;
        }
    }
    if (tid < 64) ((float*)(sm + SBIAS))[tid] = bias[g0 + tid];

    const int lq = lane >> 3, l8 = lane & 7;
    const uint32_t arow = (uint32_t)((lq & 1) * 8 + l8);
    const uint32_t akh  = (uint32_t)((lq >> 1) * 16);
    const uint32_t bgat = (uint32_t)((lq >> 1) * 8 + l8);
    const uint32_t bkh  = (uint32_t)((lq & 1) * 8);
    const int grp = lane >> 2, tig = lane & 3;

    __syncthreads();

    for (int rt = blockIdx.y; rt < 1024; rt += 24) {
        const float* Ab = A + (size_t)rt * 128 * 256;
        const int prow = tid >> 1, phalf = tid & 1;

        // prefetch k-step 0
        float4 pa0, pa1;
        {
            const float4* ap = (const float4*)(Ab + (size_t)prow * 256 + phalf * 8);
            pa0 = ap[0]; pa1 = ap[1];
        }

        float4 d[2][4];
#pragma unroll
        for (int i = 0; i < 2; ++i)
#pragma unroll
            for (int j = 0; j < 4; ++j) d[i][j] = float4{0.f, 0.f, 0.f, 0.f};

        for (int ks = 0; ks < 16; ++ks) {
            const uint32_t bsel = (uint32_t)(ks & 1) * 12288u;
            // stage current k-step into buf[ks&1]
            {
                uint4 h, l;
                split2(pa0.x, pa0.y, h.x, l.x);
                split2(pa0.z, pa0.w, h.y, l.y);
                split2(pa1.x, pa1.y, h.z, l.z);
                split2(pa1.z, pa1.w, h.w, l.w);
                *(uint4*)(sm + SA_HI + bsel + prow * 48 + phalf * 16) = h;
                *(uint4*)(sm + SA_LO + bsel + prow * 48 + phalf * 16) = l;
            }
            // prefetch next k-step (LDG latency hidden under the MMA below)
            if (ks + 1 < 16) {
                const float4* ap = (const float4*)(Ab + (size_t)prow * 256 + (ks + 1) * 16 + phalf * 8);
                pa0 = ap[0]; pa1 = ap[1];
            }
            __syncthreads();   // buf[ks&1] visible; buf[(ks+1)&1] reads long done

            uint32_t ah[2][4], al[2][4], bhr[2][4], blr[2][4];
#pragma unroll
            for (int mf = 0; mf < 2; ++mf) {
                uint32_t off = (uint32_t)((wm * 32 + mf * 16 + arow) * 48) + akh;
                ldsm4(ah[mf], sb + SA_HI + bsel + off);
                ldsm4(al[mf], sb + SA_LO + bsel + off);
            }
#pragma unroll
            for (int bp = 0; bp < 2; ++bp) {
                uint32_t off = (uint32_t)((wn * 32 + bp * 16 + bgat) * WSTRIDE)
                             + (uint32_t)((ks * 16 + bkh) * 2);
                ldsm4(bhr[bp], sb + SW_HI + off);
                ldsm4(blr[bp], sb + SW_LO + off);
            }
#pragma unroll
            for (int mf = 0; mf < 2; ++mf)
#pragma unroll
                for (int nf = 0; nf < 4; ++nf) {
                    const uint32_t* bh = &bhr[nf >> 1][(nf & 1) * 2];
                    const uint32_t* bl = &blr[nf >> 1][(nf & 1) * 2];
                    hmma(d[mf][nf], ah[mf], bh);
                    hmma(d[mf][nf], ah[mf], bl);
                    hmma(d[mf][nf], al[mf], bh);
                }
        }

        const float* bs = (const float*)(sm + SBIAS);
#pragma unroll
        for (int mf = 0; mf < 2; ++mf) {
            size_t row = (size_t)rt * 128 + wm * 32 + mf * 16 + grp;
#pragma unroll
            for (int nf = 0; nf < 4; ++nf) {
                int gc = wn * 32 + nf * 8 + 2 * tig;
                float bx = bs[gc], by = bs[gc + 1];
                float4 v = d[mf][nf];
                *(float2*)(C + row * 768 + g0 + gc)       = float2{v.x + bx, v.y + by};
                *(float2*)(C + (row + 8) * 768 + g0 + gc) = float2{v.z + bx, v.w + by};
            }
        }
    }
}

// ---------------- GRU recurrence: R10 shape + per-source mbarrier publish ----------------
// Cluster of 4 CTAs owns 4 batch rows; CTA rank owns h columns [rank*64, +64).
// 384 threads (12 warps, 3/SMSP — proven latency-hiding shape).
// Thread (gate, colpair{c,c+32}, kq): 2 cols x 4 rows x 64 k. First 32 k of the
// quarter in REGISTERS (96KB/CTA), last 32 k in SMEM (96KB).
// Publish: 8 epilogue warps each do syncwarp -> elected fence + release-arrive on
// slot[rank] at all 4 CTAs (count=8). Dot warps wait slot[kq] only -> per-source
// pipelining, no second __syncthreads, no tid0 serialization.
#define RSM_H    24576    // after 96KB weights
#define RSM_GH   26624    // [2 parity][4 kq][3 g][4 r][64 c] = 6144 floats
#define RSM_MBAR 32768    // float offset of 4 mbarrier slots
#define REC_SMEM (32768*4 + 64)

__global__ __launch_bounds__(384, 1) __cluster_dims__(4, 1, 1)
void gru_rec(const float* __restrict__ gx, const float* __restrict__ Whh,
             const float* __restrict__ bhh, float* __restrict__ out,
             float* __restrict__ hid)
{
    extern __shared__ float smem[];
    float4* sW4h = (float4*)smem;       // [gate(3)][kq(4)][kcl(8)][col(64)] float4 = 96KB
    float*  sH   = smem + RSM_H;        // double-buffered h: [2][4 rows][256]
    float*  sGh  = smem + RSM_GH;       // gh partials, parity-doubled
    const uint32_t mbar0 = smem_u32(smem) + RSM_MBAR * 4;

    const uint32_t rank = cl_rank();
    const int b0  = (blockIdx.x >> 2) * 4;
    const int tid = threadIdx.x;

    if (tid == 0)
        for (int s = 0; s < 4; ++s) mbar_init(mbar0 + s * 8, 8);

    // SMEM half: k 32..63 of each quarter -> [g][kq][kcl][col]
    for (int idx = tid; idx < 6144; idx += 384) {
        int g   = idx >> 11;
        int kqi = (idx >> 9) & 3;
        int kcl = (idx >> 6) & 7;
        int j   = idx & 63;
        int grow = g * 256 + (int)rank * 64 + j;
        int kc   = kqi * 16 + 8 + kcl;
        sW4h[idx] = ((const float4*)Whh)[grow * 64 + kc];
    }
    for (int i = tid; i < 2048; i += 384) sH[i] = 0.f;

    // dot-phase mapping (warp-uniform kq: 96 threads = 3 warps per kq)
    const int kq = tid / 96;
    const int uu = tid % 96;
    const int gg = uu >> 5;
    const int cp = uu & 31;
    const int c0 = cp, c1 = cp + 32;
    float biasA = 0.f, biasB = 0.f;
    if (kq == 0) {
        biasA = bhh[gg * 256 + (int)rank * 64 + c0];
        biasB = bhh[gg * 256 + (int)rank * 64 + c1];
    }

    // register half: k 0..31 of this thread's quarter, both cols
    u64t wrA[16], wrB[16];
    {
        const float* wbA = Whh + (size_t)(gg * 256 + (int)rank * 64 + c0) * 256 + kq * 64;
        const float* wbB = Whh + (size_t)(gg * 256 + (int)rank * 64 + c1) * 256 + kq * 64;
#pragma unroll
        for (int kk = 0; kk < 8; ++kk) {
            ulonglong2 a = *(const ulonglong2*)(wbA + kk * 4);
            ulonglong2 b = *(const ulonglong2*)(wbB + kk * 4);
            wrA[2 * kk] = a.x; wrA[2 * kk + 1] = a.y;
            wrB[2 * kk] = b.x; wrB[2 * kk + 1] = b.y;
        }
    }

    // epilogue mapping (tid < 256 = warps 0..7)
    const int erow = (tid >> 6) & 3;
    const int ecol = tid & 63;
    const size_t gxBase  = ((size_t)(b0 + erow) * 1024) * 768 + rank * 64 + ecol;
    const size_t outBase = ((size_t)(b0 + erow) * 1024) * 256 + rank * 64 + ecol;

    float gxr = 0.f, gxz = 0.f, gxn = 0.f;
    if (tid < 256) {
        gxr = gx[gxBase];
        gxz = gx[gxBase + 256];
        gxn = gx[gxBase + 512];
    }

    cl_sync();  // smem weights, zeroed h, mbarrier inits visible cluster-wide

    const uint32_t myslot = mbar0 + (uint32_t)kq * 8;

    for (int t = 0; t < 1024; ++t) {
        // h chunk kq of step t was published by CTA kq's 8 epilogue warps at the
        // end of step t-1 (local CTA included — orders local h writes too).
        if (t > 0)
            mbar_wait_parity_cluster(myslot, (uint32_t)((t - 1) & 1));

        // ---- dot phase ----
        {
            const float* hb = sH + (t & 1) * 1024 + kq * 64;
            u64t acc[8];
#pragma unroll
            for (int i = 0; i < 8; ++i) acc[i] = 0ull;
            // part A: k 0..31 of quarter, weights from registers
#pragma unroll
            for (int kk = 0; kk < 8; ++kk) {
                u64t wax = wrA[2 * kk], way = wrA[2 * kk + 1];
                u64t wbx = wrB[2 * kk], wby = wrB[2 * kk + 1];
#pragma unroll
                for (int r = 0; r < 4; ++r) {
                    ulonglong2 hv = *(const ulonglong2*)(hb + r * 256 + kk * 4);
                    acc[r]     = ffma2(wax, hv.x, acc[r]);
                    acc[r]     = ffma2(way, hv.y, acc[r]);
                    acc[4 + r] = ffma2(wbx, hv.x, acc[4 + r]);
                    acc[4 + r] = ffma2(wby, hv.y, acc[4 + r]);
                }
            }
            // part B: k 32..63 of quarter, weights from SMEM
            const float4* wq = sW4h + (size_t)((gg * 4 + kq) * 8) * 64;
#pragma unroll
            for (int kk = 0; kk < 8; ++kk) {
                ulonglong2 wA = *(const ulonglong2*)(wq + kk * 64 + c0);
                ulonglong2 wB = *(const ulonglong2*)(wq + kk * 64 + c1);
#pragma unroll
                for (int r = 0; r < 4; ++r) {
                    ulonglong2 hv = *(const ulonglong2*)(hb + r * 256 + (8 + kk) * 4);
                    acc[r]     = ffma2(wA.x, hv.x, acc[r]);
                    acc[r]     = ffma2(wA.y, hv.y, acc[r]);
                    acc[4 + r] = ffma2(wB.x, hv.x, acc[4 + r]);
                    acc[4 + r] = ffma2(wB.y, hv.y, acc[4 + r]);
                }
            }
            float* sg = sGh + (t & 1) * 3072 + kq * 768 + gg * 256;
#pragma unroll
            for (int r = 0; r < 4; ++r) {
                float2 pa = unpack2(acc[r]);
                float2 pb = unpack2(acc[4 + r]);
                sg[r * 64 + c0] = pa.x + pa.y + biasA;
                sg[r * 64 + c1] = pb.x + pb.y + biasB;
            }
        }
        __syncthreads();   // sGh(t) complete before epilogue reads

        // ---- epilogue: warps 0..7 ----
        if (tid < 256) {
            const float* sg2 = sGh + (t & 1) * 3072;
            const int o = erow * 64 + ecol;
            float ghr = sg2[o]       + sg2[768 + o]       + sg2[1536 + o]       + sg2[2304 + o];
            float ghz = sg2[256 + o] + sg2[768 + 256 + o] + sg2[1536 + 256 + o] + sg2[2304 + 256 + o];
            float ghn = sg2[512 + o] + sg2[768 + 512 + o] + sg2[1536 + 512 + o] + sg2[2304 + 512 + o];

            float r  = fast_sigmoid(gxr + ghr);
            float z  = fast_sigmoid(gxz + ghz);
            float hp = sH[(t & 1) * 1024 + erow * 256 + rank * 64 + ecol];
            float n  = fast_tanh(fmaf(r, ghn, gxn));
            float hnew = fmaf(z, hp - n, n);   // (1-z)*n + z*hp

            float* hdst = sH + ((t + 1) & 1) * 1024 + erow * 256 + rank * 64 + ecol;
            *hdst = hnew;
            uint32_t laddr = smem_u32(hdst);
#pragma unroll
            for (int pr = 0; pr < 4; ++pr)
                if (pr != (int)rank) st_cl_f32(cl_map(laddr, (uint32_t)pr), hnew);

            // per-warp publish: my warp's stores done -> release-arrive on
            // slot[rank] at every CTA (count 8 = 8 epilogue warps)
            __syncwarp();
            if (elect1()) {
                asm volatile("fence.acq_rel.cluster;" ::: "memory");
                uint32_t slotR = mbar0 + rank * 8;
#pragma unroll
                for (int pr = 0; pr < 4; ++pr) mbar_arrive_cluster(slotR, (uint32_t)pr);
            }

            // hidden under publish latency: out store + next-step gx prefetch
            out[outBase + (size_t)t * 256] = hnew;
            if (t + 1 < 1024) {
                size_t gbase = gxBase + (size_t)(t + 1) * 768;
                gxr = gx[gbase];
                gxz = gx[gbase + 256];
                gxn = gx[gbase + 512];
            }
        }
    }

    if (tid < 256)   // this thread itself wrote this element in the final epilogue
        hid[(size_t)(b0 + erow) * 256 + rank * 64 + ecol] =
            sH[erow * 256 + rank * 64 + ecol];   // final buffer = (1024 & 1) = 0
    cl_sync();  // no CTA exits while peers may still target its SMEM
}

// ---------------- launch ----------------
extern "C" void kernel_launch(void* const* d_in, const int* in_sizes, int n_in,
                              void* d_out, int out_size)
{
    const float* X      = (const float*)d_in[0];
    const float* w_ih_0 = (const float*)d_in[1];
    const float* w_hh_0 = (const float*)d_in[2];
    const float* b_ih_0 = (const float*)d_in[3];
    const float* b_hh_0 = (const float*)d_in[4];
    const float* w_ih_1 = (const float*)d_in[5];
    const float* w_hh_1 = (const float*)d_in[6];
    const float* b_ih_1 = (const float*)d_in[7];
    const float* b_hh_1 = (const float*)d_in[8];

    float* out1 = (float*)d_out;
    float* hid  = out1 + (size_t)ROWS * Mm;

    float *gx = nullptr, *o0 = nullptr;
    cudaGetSymbolAddress((void**)&gx, g_gx);
    cudaGetSymbolAddress((void**)&o0, g_out0);

    cudaFuncSetAttribute(gru_rec, cudaFuncAttributeMaxDynamicSharedMemorySize, REC_SMEM);
    cudaFuncSetAttribute(gemm_hmma, cudaFuncAttributeMaxDynamicSharedMemorySize, SM_GEMM);

    dim3 ggrid(12, 24);   // 12 gate-tiles x 24 row-streams

    // layer 0
    gemm_hmma<<<ggrid, 256, SM_GEMM>>>(X, w_ih_0, b_ih_0, gx);
    gru_rec<<<128, 384, REC_SMEM>>>(gx, w_hh_0, b_hh_0, o0, hid);
    // layer 1
    gemm_hmma<<<ggrid, 256, SM_GEMM>>>(o0, w_ih_1, b_ih_1, gx);
    gru_rec<<<128, 384, REC_SMEM>>>(gx, w_hh_1, b_hh_1, out1, hid + (size_t)Bb * Mm);
}

// round 14
// speedup vs baseline: 1.9696x; 1.3885x over previous
#include <cuda_runtime.h>
#include <cuda_bf16.h>
#include <cstdint>
#include <math.h>

#define Bb 128
#define Tt 1024
#define Nn 256
#define Mm 256
#define Gg 768
#define ROWS (Bb*Tt)

// Scratch (allocation-free rule: __device__ globals)
__device__ float g_gx[(size_t)ROWS * Gg];    // input-gate activations
__device__ float g_out0[(size_t)ROWS * Mm];  // layer-0 output

typedef unsigned long long u64t;

// ---------------- packed f32x2 helpers ----------------
__device__ __forceinline__ u64t ffma2(u64t a, u64t b, u64t c) {
    u64t d;
    asm("fma.rn.f32x2 %0, %1, %2, %3;" : "=l"(d) : "l"(a), "l"(b), "l"(c));
    return d;
}
__device__ __forceinline__ float2 unpack2(u64t v) {
    float2 r; asm("mov.b64 {%0, %1}, %2;" : "=f"(r.x), "=f"(r.y) : "l"(v)); return r;
}

// ---------------- cluster / DSMEM helpers ----------------
__device__ __forceinline__ uint32_t smem_u32(const void* p) {
    uint32_t a;
    asm("{ .reg .u64 t; cvta.to.shared.u64 t, %1; cvt.u32.u64 %0, t; }" : "=r"(a) : "l"(p));
    return a;
}
__device__ __forceinline__ uint32_t cl_rank() {
    uint32_t r; asm("mov.u32 %0, %%cluster_ctarank;" : "=r"(r)); return r;
}
__device__ __forceinline__ uint32_t cl_map(uint32_t addr, uint32_t rank) {
    uint32_t r; asm("mapa.shared::cluster.u32 %0, %1, %2;" : "=r"(r) : "r"(addr), "r"(rank)); return r;
}
__device__ __forceinline__ void st_cl_f32(uint32_t addr, float v) {
    asm volatile("st.shared::cluster.f32 [%0], %1;" :: "r"(addr), "f"(v) : "memory");
}
__device__ __forceinline__ void cl_sync() {
    asm volatile("barrier.cluster.arrive.aligned;" ::: "memory");
    asm volatile("barrier.cluster.wait.aligned;" ::: "memory");
}

// ---------------- mbarrier helpers ----------------
__device__ __forceinline__ void mbar_init(uint32_t a, uint32_t cnt) {
    asm volatile("mbarrier.init.shared.b64 [%0], %1;" :: "r"(a), "r"(cnt) : "memory");
}
__device__ __forceinline__ void mbar_arrive_cluster(uint32_t local_addr, uint32_t pr) {
    asm volatile(
        "{\n\t.reg .b32 ra;\n\t"
        "mapa.shared::cluster.u32 ra, %0, %1;\n\t"
        "mbarrier.arrive.shared::cluster.b64 _, [ra];\n\t}"
        :: "r"(local_addr), "r"(pr) : "memory");
}
__device__ __forceinline__ void mbar_wait_parity_cluster(uint32_t a, uint32_t parity) {
    asm volatile(
        "{\n\t.reg .pred P1;\n\t"
        "WL_%=:\n\t"
        "mbarrier.try_wait.parity.acquire.cluster.shared::cta.b64 P1, [%0], %1, 0x989680;\n\t"
        "@P1 bra.uni WD_%=;\n\t"
        "bra.uni WL_%=;\n\t"
        "WD_%=:\n\t}"
        :: "r"(a), "r"(parity) : "memory");
}

__device__ __forceinline__ float fast_sigmoid(float x) {
    return 1.f / (1.f + __expf(-x));
}
__device__ __forceinline__ float fast_tanh(float x) {
    return 1.f - __fdividef(2.f, 1.f + __expf(2.f * x));
}

// ---------------- warp-MMA helpers (baseline ISA, no tcgen05) ----------------
__device__ __forceinline__ void ldsm4(uint32_t r[4], uint32_t addr) {
    asm volatile("ldmatrix.sync.aligned.m8n8.x4.shared.b16 {%0,%1,%2,%3}, [%4];"
                 : "=r"(r[0]), "=r"(r[1]), "=r"(r[2]), "=r"(r[3]) : "r"(addr));
}
__device__ __forceinline__ void hmma(float4& d, const uint32_t a[4], const uint32_t* b) {
    asm volatile("mma.sync.aligned.m16n8k16.row.col.f32.bf16.bf16.f32 "
                 "{%0,%1,%2,%3}, {%4,%5,%6,%7}, {%8,%9}, {%0,%1,%2,%3};"
                 : "+f"(d.x), "+f"(d.y), "+f"(d.z), "+f"(d.w)
                 : "r"(a[0]), "r"(a[1]), "r"(a[2]), "r"(a[3]), "r"(b[0]), "r"(b[1]));
}

// split fp32 -> bf16 hi + bf16 residual, pack pairs into u32
__device__ __forceinline__ void split2(float x, float y, uint32_t& hi, uint32_t& lo) {
    __nv_bfloat16 hx = __float2bfloat16(x);
    __nv_bfloat16 hy = __float2bfloat16(y);
    __nv_bfloat16 lx = __float2bfloat16(x - __bfloat162float(hx));
    __nv_bfloat16 ly = __float2bfloat16(y - __bfloat162float(hy));
    hi = (uint32_t)*(uint16_t*)&hx | ((uint32_t)*(uint16_t*)&hy << 16);
    lo = (uint32_t)*(uint16_t*)&lx | ((uint32_t)*(uint16_t*)&ly << 16);
}

// ---------------- input-gate GEMM via mma.sync bf16x3 (fp32-accurate) ----------------
// Double-buffered A staging: ONE __syncthreads per k-step. (R12 — kept, ~100us win)
#define SW_HI   0
#define SW_LO   33792
#define SA_HI   67584     // + bufsel*12288
#define SA_LO   73728     // = SA_HI + 6144
#define SBIAS   92160
#define SM_GEMM 92416
#define WSTRIDE 528   // bytes per gate row (256 bf16 + 8 pad)

__global__ __launch_bounds__(256, 2) void gemm_hmma(
    const float* __restrict__ A, const float* __restrict__ W,
    const float* __restrict__ bias, float* __restrict__ C)
{
    extern __shared__ char sm[];
    const uint32_t sb = smem_u32(sm);
    const int tid  = threadIdx.x;
    const int lane = tid & 31, warp = tid >> 5;
    const int wm = warp >> 1, wn = warp & 1;
    const int g0 = blockIdx.x * 64;

    // one-time: W tile fp32 -> bf16 hi/lo SMEM
    {
        const int r = tid >> 2, kq = tid & 3;
        const float4* wp = (const float4*)(W + (size_t)(g0 + r) * 256 + kq * 64);
        char* dh = sm + SW_HI + r * WSTRIDE + kq * 128;
        char* dl = sm + SW_LO + r * WSTRIDE + kq * 128;
#pragma unroll
        for (int kk = 0; kk < 16; ++kk) {
            float4 v = wp[kk];
            uint2 h, l;
            split2(v.x, v.y, h.x, l.x);
            split2(v.z, v.w, h.y, l.y);
            *(uint2*)(dh + kk * 8) = h;
            *(uint2*)(dl + kk * 8) = l;
        }
    }
    if (tid < 64) ((float*)(sm + SBIAS))[tid] = bias[g0 + tid];

    const int lq = lane >> 3, l8 = lane & 7;
    const uint32_t arow = (uint32_t)((lq & 1) * 8 + l8);
    const uint32_t akh  = (uint32_t)((lq >> 1) * 16);
    const uint32_t bgat = (uint32_t)((lq >> 1) * 8 + l8);
    const uint32_t bkh  = (uint32_t)((lq & 1) * 8);
    const int grp = lane >> 2, tig = lane & 3;

    __syncthreads();

    for (int rt = blockIdx.y; rt < 1024; rt += 24) {
        const float* Ab = A + (size_t)rt * 128 * 256;
        const int prow = tid >> 1, phalf = tid & 1;

        float4 pa0, pa1;
        {
            const float4* ap = (const float4*)(Ab + (size_t)prow * 256 + phalf * 8);
            pa0 = ap[0]; pa1 = ap[1];
        }

        float4 d[2][4];
#pragma unroll
        for (int i = 0; i < 2; ++i)
#pragma unroll
            for (int j = 0; j < 4; ++j) d[i][j] = float4{0.f, 0.f, 0.f, 0.f};

        for (int ks = 0; ks < 16; ++ks) {
            const uint32_t bsel = (uint32_t)(ks & 1) * 12288u;
            {
                uint4 h, l;
                split2(pa0.x, pa0.y, h.x, l.x);
                split2(pa0.z, pa0.w, h.y, l.y);
                split2(pa1.x, pa1.y, h.z, l.z);
                split2(pa1.z, pa1.w, h.w, l.w);
                *(uint4*)(sm + SA_HI + bsel + prow * 48 + phalf * 16) = h;
                *(uint4*)(sm + SA_LO + bsel + prow * 48 + phalf * 16) = l;
            }
            if (ks + 1 < 16) {
                const float4* ap = (const float4*)(Ab + (size_t)prow * 256 + (ks + 1) * 16 + phalf * 8);
                pa0 = ap[0]; pa1 = ap[1];
            }
            __syncthreads();

            uint32_t ah[2][4], al[2][4], bhr[2][4], blr[2][4];
#pragma unroll
            for (int mf = 0; mf < 2; ++mf) {
                uint32_t off = (uint32_t)((wm * 32 + mf * 16 + arow) * 48) + akh;
                ldsm4(ah[mf], sb + SA_HI + bsel + off);
                ldsm4(al[mf], sb + SA_LO + bsel + off);
            }
#pragma unroll
            for (int bp = 0; bp < 2; ++bp) {
                uint32_t off = (uint32_t)((wn * 32 + bp * 16 + bgat) * WSTRIDE)
                             + (uint32_t)((ks * 16 + bkh) * 2);
                ldsm4(bhr[bp], sb + SW_HI + off);
                ldsm4(blr[bp], sb + SW_LO + off);
            }
#pragma unroll
            for (int mf = 0; mf < 2; ++mf)
#pragma unroll
                for (int nf = 0; nf < 4; ++nf) {
                    const uint32_t* bh = &bhr[nf >> 1][(nf & 1) * 2];
                    const uint32_t* bl = &blr[nf >> 1][(nf & 1) * 2];
                    hmma(d[mf][nf], ah[mf], bh);
                    hmma(d[mf][nf], ah[mf], bl);
                    hmma(d[mf][nf], al[mf], bh);
                }
        }

        const float* bs = (const float*)(sm + SBIAS);
#pragma unroll
        for (int mf = 0; mf < 2; ++mf) {
            size_t row = (size_t)rt * 128 + wm * 32 + mf * 16 + grp;
#pragma unroll
            for (int nf = 0; nf < 4; ++nf) {
                int gc = wn * 32 + nf * 8 + 2 * tig;
                float bx = bs[gc], by = bs[gc + 1];
                float4 v = d[mf][nf];
                *(float2*)(C + row * 768 + g0 + gc)       = float2{v.x + bx, v.y + by};
                *(float2*)(C + (row + 8) * 768 + g0 + gc) = float2{v.z + bx, v.w + by};
            }
        }
    }
}

// ---------------- GRU recurrence v4: gate-merged mapping, 16 warps ----------------
// Cluster of 4 CTAs owns 4 batch rows; CTA rank owns h columns [rank*64, +64).
// 512 threads = (c 0..63) x (k-eighth e 0..7). Thread computes ALL 3 gates x 4 rows
// x 32 k for its (c, e):
//   r,z gate weights: 64 REGISTERS per thread (no LDS).  n gate: SMEM 64KB.
// Crossbar/step: 512 wf (n-weights) + 512 wf (h broadcast) + ~290 staging < 1536 FMA.
// 16 warps = 4/SMSP (R11 failed at 2/SMSP; R10 had 3).
// Publish/wait mechanism = R10 verbatim (sync2 -> tid0 fence + 4 arrives, count=4;
// dot warps wait only if their h chunk (e>>1) is remote).
#define RSM_WN   0        // n-gate weights: [k4(64)][c(64)] float4 = 16384 floats
#define RSM_H    16384    // h double buffer: [2][4 rows][256] = 2048 floats
#define RSM_GH   18432    // gh partials: [e(8)][g(3)][r(4)][c(64)] = 6144 floats
#define RSM_MBAR 24576    // float offset of mbarrier (byte 98304, 8B aligned)
#define REC_SMEM (24576*4 + 64)

__global__ __launch_bounds__(512, 1) __cluster_dims__(4, 1, 1)
void gru_rec(const float* __restrict__ gx, const float* __restrict__ Whh,
             const float* __restrict__ bhh, float* __restrict__ out,
             float* __restrict__ hid)
{
    extern __shared__ float smem[];
    float4* sWn4 = (float4*)smem;       // n-gate weights [k4][c]
    float*  sH   = smem + RSM_H;        // double-buffered h
    float*  sGh  = smem + RSM_GH;       // gh partials
    const uint32_t mbarA = smem_u32(smem) + RSM_MBAR * 4;

    const uint32_t rank = cl_rank();
    const int b0  = (blockIdx.x >> 2) * 4;
    const int tid = threadIdx.x;
    const int e   = tid >> 6;          // k-eighth, warp-uniform (2 warps per e)
    const int c   = tid & 63;          // column within this CTA's 64-col chunk

    if (tid == 0) mbar_init(mbarA, 4);

    // n-gate weights -> SMEM [k4][c] float4 (k4 = k/4, 64 entries)
    for (int idx = tid; idx < 4096; idx += 512) {
        int k4 = idx >> 6, j = idx & 63;
        sWn4[idx] = ((const float4*)Whh)[(size_t)(512 + rank * 64 + j) * 64 + k4];
    }
    for (int i = tid; i < 2048; i += 512) sH[i] = 0.f;

    // r,z gate weights for (c, k in [e*32, e*32+32)) -> 64 registers
    u64t wrR[16], wrZ[16];
    {
        const float* wbR = Whh + (size_t)(rank * 64 + c) * 256 + e * 32;
        const float* wbZ = wbR + 256 * 256;
#pragma unroll
        for (int kk = 0; kk < 8; ++kk) {
            ulonglong2 a = *(const ulonglong2*)(wbR + kk * 4);
            ulonglong2 b = *(const ulonglong2*)(wbZ + kk * 4);
            wrR[2 * kk] = a.x; wrR[2 * kk + 1] = a.y;
            wrZ[2 * kk] = b.x; wrZ[2 * kk + 1] = b.y;
        }
    }

    // epilogue mapping (tid < 256): one h element (erow, ecol)
    const int erow = (tid >> 6) & 3;
    const int ecol = tid & 63;
    float bR = 0.f, bZ = 0.f, bN = 0.f;
    if (tid < 256) {
        bR = bhh[rank * 64 + ecol];
        bZ = bhh[256 + rank * 64 + ecol];
        bN = bhh[512 + rank * 64 + ecol];
    }
    const size_t gxBase  = ((size_t)(b0 + erow) * 1024) * 768 + rank * 64 + ecol;
    const size_t outBase = ((size_t)(b0 + erow) * 1024) * 256 + rank * 64 + ecol;

    float gxr = 0.f, gxz = 0.f, gxn = 0.f;
    if (tid < 256) {
        gxr = gx[gxBase];
        gxz = gx[gxBase + 256];
        gxn = gx[gxBase + 512];
    }

    cl_sync();  // smem weights, zeroed h, mbarrier init visible cluster-wide

    const bool locale = ((e >> 1) == (int)rank);   // h chunk produced locally?

    for (int t = 0; t < 1024; ++t) {
        // h cols [ (e>>1)*64, +64 ) of step t published by CTA (e>>1) at end of
        // step t-1. Local chunks are ordered by sync2; remote warps wait.
        if (t > 0 && !locale)
            mbar_wait_parity_cluster(mbarA, (uint32_t)((t - 1) & 1));

        // ---- dot: 3 gates x 4 rows x 32 k, column c ----
        {
            const float* hb = sH + (t & 1) * 1024 + e * 32;   // k-offset within row
            const float4* wn = sWn4 + e * 8 * 64 + c;         // k4 stride 64
            u64t aR[4], aZ[4], aN[4];
#pragma unroll
            for (int i = 0; i < 4; ++i) { aR[i] = 0ull; aZ[i] = 0ull; aN[i] = 0ull; }
#pragma unroll
            for (int kk = 0; kk < 8; ++kk) {
                ulonglong2 wnv = *(const ulonglong2*)(wn + kk * 64);
                u64t wr0 = wrR[2 * kk], wr1 = wrR[2 * kk + 1];
                u64t wz0 = wrZ[2 * kk], wz1 = wrZ[2 * kk + 1];
#pragma unroll
                for (int r = 0; r < 4; ++r) {
                    ulonglong2 hv = *(const ulonglong2*)(hb + r * 256 + kk * 4);
                    aR[r] = ffma2(wr0, hv.x, aR[r]);
                    aR[r] = ffma2(wr1, hv.y, aR[r]);
                    aZ[r] = ffma2(wz0, hv.x, aZ[r]);
                    aZ[r] = ffma2(wz1, hv.y, aZ[r]);
                    aN[r] = ffma2(wnv.x, hv.x, aN[r]);
                    aN[r] = ffma2(wnv.y, hv.y, aN[r]);
                }
            }
            float* sg = sGh + e * 768 + c;     // [e][g][r][c]
#pragma unroll
            for (int r = 0; r < 4; ++r) {
                float2 pr2 = unpack2(aR[r]);
                float2 pz2 = unpack2(aZ[r]);
                float2 pn2 = unpack2(aN[r]);
                sg[r * 64]        = pr2.x + pr2.y;
                sg[256 + r * 64]  = pz2.x + pz2.y;
                sg[512 + r * 64]  = pn2.x + pn2.y;
            }
        }
        __syncthreads();   // sGh complete before epilogue reads

        // ---- epilogue: warps 0..7, one element each ----
        float hnew = 0.f;
        if (tid < 256) {
            const int o = erow * 64 + ecol;
            float ghr = 0.f, ghz = 0.f, ghn = 0.f;
#pragma unroll
            for (int ee = 0; ee < 8; ++ee) {
                ghr += sGh[ee * 768 + o];
                ghz += sGh[ee * 768 + 256 + o];
                ghn += sGh[ee * 768 + 512 + o];
            }
            float r  = fast_sigmoid(gxr + ghr + bR);
            float z  = fast_sigmoid(gxz + ghz + bZ);
            float hp = sH[(t & 1) * 1024 + erow * 256 + rank * 64 + ecol];
            float n  = fast_tanh(fmaf(r, ghn + bN, gxn));
            hnew = fmaf(z, hp - n, n);   // (1-z)*n + z*hp

            float* hdst = sH + ((t + 1) & 1) * 1024 + erow * 256 + rank * 64 + ecol;
            *hdst = hnew;
            uint32_t laddr = smem_u32(hdst);
#pragma unroll
            for (int pr = 0; pr < 4; ++pr)
                if (pr != (int)rank) st_cl_f32(cl_map(laddr, (uint32_t)pr), hnew);
        }
        __syncthreads();  // all h stores issued before the signal; sGh reusable

        if (tid == 0) {
            asm volatile("fence.acq_rel.cluster;" ::: "memory");  // publish DSMEM writes
#pragma unroll
            for (int pr = 0; pr < 4; ++pr) mbar_arrive_cluster(mbarA, (uint32_t)pr);
        }
        // hidden under publish latency: out store + next-step gx prefetch
        if (tid < 256) {
            out[outBase + (size_t)t * 256] = hnew;
            if (t + 1 < 1024) {
                size_t gbase = gxBase + (size_t)(t + 1) * 768;
                gxr = gx[gbase];
                gxz = gx[gbase + 256];
                gxn = gx[gbase + 512];
            }
        }
    }

    if (tid < 256)
        hid[(size_t)(b0 + erow) * 256 + rank * 64 + ecol] =
            sH[erow * 256 + rank * 64 + ecol];   // final buffer = (1024 & 1) = 0
    cl_sync();  // no CTA exits while peers may still target its SMEM
}

// ---------------- launch ----------------
extern "C" void kernel_launch(void* const* d_in, const int* in_sizes, int n_in,
                              void* d_out, int out_size)
{
    const float* X      = (const float*)d_in[0];
    const float* w_ih_0 = (const float*)d_in[1];
    const float* w_hh_0 = (const float*)d_in[2];
    const float* b_ih_0 = (const float*)d_in[3];
    const float* b_hh_0 = (const float*)d_in[4];
    const float* w_ih_1 = (const float*)d_in[5];
    const float* w_hh_1 = (const float*)d_in[6];
    const float* b_ih_1 = (const float*)d_in[7];
    const float* b_hh_1 = (const float*)d_in[8];

    float* out1 = (float*)d_out;
    float* hid  = out1 + (size_t)ROWS * Mm;

    float *gx = nullptr, *o0 = nullptr;
    cudaGetSymbolAddress((void**)&gx, g_gx);
    cudaGetSymbolAddress((void**)&o0, g_out0);

    cudaFuncSetAttribute(gru_rec, cudaFuncAttributeMaxDynamicSharedMemorySize, REC_SMEM);
    cudaFuncSetAttribute(gemm_hmma, cudaFuncAttributeMaxDynamicSharedMemorySize, SM_GEMM);

    dim3 ggrid(12, 24);   // 12 gate-tiles x 24 row-streams

    // layer 0
    gemm_hmma<<<ggrid, 256, SM_GEMM>>>(X, w_ih_0, b_ih_0, gx);
    gru_rec<<<128, 512, REC_SMEM>>>(gx, w_hh_0, b_hh_0, o0, hid);
    // layer 1
    gemm_hmma<<<ggrid, 256, SM_GEMM>>>(o0, w_ih_1, b_ih_1, gx);
    gru_rec<<<128, 512, REC_SMEM>>>(gx, w_hh_1, b_hh_1, out1, hid + (size_t)Bb * Mm);
}

// round 16
// speedup vs baseline: 2.0165x; 1.0238x over previous
#include <cuda_runtime.h>
#include <cuda_bf16.h>
#include <cstdint>
#include <math.h>

#define Bb 128
#define Tt 1024
#define Nn 256
#define Mm 256
#define Gg 768
#define ROWS (Bb*Tt)

// Scratch (allocation-free rule: __device__ globals)
__device__ float g_gx[(size_t)ROWS * Gg];    // input-gate activations
__device__ float g_out0[(size_t)ROWS * Mm];  // layer-0 output

typedef unsigned long long u64t;

// ---------------- packed f32x2 helpers ----------------
__device__ __forceinline__ u64t ffma2(u64t a, u64t b, u64t c) {
    u64t d;
    asm("fma.rn.f32x2 %0, %1, %2, %3;" : "=l"(d) : "l"(a), "l"(b), "l"(c));
    return d;
}
__device__ __forceinline__ float2 unpack2(u64t v) {
    float2 r; asm("mov.b64 {%0, %1}, %2;" : "=f"(r.x), "=f"(r.y) : "l"(v)); return r;
}

// ---------------- cluster / DSMEM helpers ----------------
__device__ __forceinline__ uint32_t smem_u32(const void* p) {
    uint32_t a;
    asm("{ .reg .u64 t; cvta.to.shared.u64 t, %1; cvt.u32.u64 %0, t; }" : "=r"(a) : "l"(p));
    return a;
}
__device__ __forceinline__ uint32_t cl_rank() {
    uint32_t r; asm("mov.u32 %0, %%cluster_ctarank;" : "=r"(r)); return r;
}
__device__ __forceinline__ uint32_t cl_map(uint32_t addr, uint32_t rank) {
    uint32_t r; asm("mapa.shared::cluster.u32 %0, %1, %2;" : "=r"(r) : "r"(addr), "r"(rank)); return r;
}
__device__ __forceinline__ void st_cl_f32(uint32_t addr, float v) {
    asm volatile("st.shared::cluster.f32 [%0], %1;" :: "r"(addr), "f"(v) : "memory");
}
__device__ __forceinline__ void cl_sync() {
    asm volatile("barrier.cluster.arrive.aligned;" ::: "memory");
    asm volatile("barrier.cluster.wait.aligned;" ::: "memory");
}

// ---------------- mbarrier helpers ----------------
__device__ __forceinline__ void mbar_init(uint32_t a, uint32_t cnt) {
    asm volatile("mbarrier.init.shared.b64 [%0], %1;" :: "r"(a), "r"(cnt) : "memory");
}
__device__ __forceinline__ void mbar_arrive_cluster(uint32_t local_addr, uint32_t pr) {
    asm volatile(
        "{\n\t.reg .b32 ra;\n\t"
        "mapa.shared::cluster.u32 ra, %0, %1;\n\t"
        "mbarrier.arrive.shared::cluster.b64 _, [ra];\n\t}"
        :: "r"(local_addr), "r"(pr) : "memory");
}
__device__ __forceinline__ void mbar_wait_parity_cluster(uint32_t a, uint32_t parity) {
    asm volatile(
        "{\n\t.reg .pred P1;\n\t"
        "WL_%=:\n\t"
        "mbarrier.try_wait.parity.acquire.cluster.shared::cta.b64 P1, [%0], %1, 0x989680;\n\t"
        "@P1 bra.uni WD_%=;\n\t"
        "bra.uni WL_%=;\n\t"
        "WD_%=:\n\t}"
        :: "r"(a), "r"(parity) : "memory");
}

__device__ __forceinline__ float fast_sigmoid(float x) {
    return 1.f / (1.f + __expf(-x));
}
__device__ __forceinline__ float fast_tanh(float x) {
    return 1.f - __fdividef(2.f, 1.f + __expf(2.f * x));
}

// ---------------- warp-MMA helpers (baseline ISA, no tcgen05) ----------------
__device__ __forceinline__ void ldsm4(uint32_t r[4], uint32_t addr) {
    asm volatile("ldmatrix.sync.aligned.m8n8.x4.shared.b16 {%0,%1,%2,%3}, [%4];"
                 : "=r"(r[0]), "=r"(r[1]), "=r"(r[2]), "=r"(r[3]) : "r"(addr));
}
__device__ __forceinline__ void hmma(float4& d, const uint32_t a[4], const uint32_t* b) {
    asm volatile("mma.sync.aligned.m16n8k16.row.col.f32.bf16.bf16.f32 "
                 "{%0,%1,%2,%3}, {%4,%5,%6,%7}, {%8,%9}, {%0,%1,%2,%3};"
                 : "+f"(d.x), "+f"(d.y), "+f"(d.z), "+f"(d.w)
                 : "r"(a[0]), "r"(a[1]), "r"(a[2]), "r"(a[3]), "r"(b[0]), "r"(b[1]));
}

// split fp32 -> bf16 hi + bf16 residual, pack pairs into u32
__device__ __forceinline__ void split2(float x, float y, uint32_t& hi, uint32_t& lo) {
    __nv_bfloat16 hx = __float2bfloat16(x);
    __nv_bfloat16 hy = __float2bfloat16(y);
    __nv_bfloat16 lx = __float2bfloat16(x - __bfloat162float(hx));
    __nv_bfloat16 ly = __float2bfloat16(y - __bfloat162float(hy));
    hi = (uint32_t)*(uint16_t*)&hx | ((uint32_t)*(uint16_t*)&hy << 16);
    lo = (uint32_t)*(uint16_t*)&lx | ((uint32_t)*(uint16_t*)&ly << 16);
}

// ---------------- input-gate GEMM via mma.sync bf16x3 (fp32-accurate) ----------------
// Double-buffered A staging: ONE __syncthreads per k-step.
#define SW_HI   0
#define SW_LO   33792
#define SA_HI   67584     // + bufsel*12288
#define SA_LO   73728     // = SA_HI + 6144
#define SBIAS   92160
#define SM_GEMM 92416
#define WSTRIDE 528   // bytes per gate row (256 bf16 + 8 pad)

__global__ __launch_bounds__(256, 2) void gemm_hmma(
    const float* __restrict__ A, const float* __restrict__ W,
    const float* __restrict__ bias, float* __restrict__ C)
{
    extern __shared__ char sm[];
    const uint32_t sb = smem_u32(sm);
    const int tid  = threadIdx.x;
    const int lane = tid & 31, warp = tid >> 5;
    const int wm = warp >> 1, wn = warp & 1;
    const int g0 = blockIdx.x * 64;

    // one-time: W tile fp32 -> bf16 hi/lo SMEM
    {
        const int r = tid >> 2, kq = tid & 3;
        const float4* wp = (const float4*)(W + (size_t)(g0 + r) * 256 + kq * 64);
        char* dh = sm + SW_HI + r * WSTRIDE + kq * 128;
        char* dl = sm + SW_LO + r * WSTRIDE + kq * 128;
#pragma unroll
        for (int kk = 0; kk < 16; ++kk) {
            float4 v = wp[kk];
            uint2 h, l;
            split2(v.x, v.y, h.x, l.x);
            split2(v.z, v.w, h.y, l.y);
            *(uint2*)(dh + kk * 8) = h;
            *(uint2*)(dl + kk * 8) = l;
        }
    }
    if (tid < 64) ((float*)(sm + SBIAS))[tid] = bias[g0 + tid];

    const int lq = lane >> 3, l8 = lane & 7;
    const uint32_t arow = (uint32_t)((lq & 1) * 8 + l8);
    const uint32_t akh  = (uint32_t)((lq >> 1) * 16);
    const uint32_t bgat = (uint32_t)((lq >> 1) * 8 + l8);
    const uint32_t bkh  = (uint32_t)((lq & 1) * 8);
    const int grp = lane >> 2, tig = lane & 3;

    __syncthreads();

    for (int rt = blockIdx.y; rt < 1024; rt += 24) {
        const float* Ab = A + (size_t)rt * 128 * 256;
        const int prow = tid >> 1, phalf = tid & 1;

        float4 pa0, pa1;
        {
            const float4* ap = (const float4*)(Ab + (size_t)prow * 256 + phalf * 8);
            pa0 = ap[0]; pa1 = ap[1];
        }

        float4 d[2][4];
#pragma unroll
        for (int i = 0; i < 2; ++i)
#pragma unroll
            for (int j = 0; j < 4; ++j) d[i][j] = float4{0.f, 0.f, 0.f, 0.f};

        for (int ks = 0; ks < 16; ++ks) {
            const uint32_t bsel = (uint32_t)(ks & 1) * 12288u;
            {
                uint4 h, l;
                split2(pa0.x, pa0.y, h.x, l.x);
                split2(pa0.z, pa0.w, h.y, l.y);
                split2(pa1.x, pa1.y, h.z, l.z);
                split2(pa1.z, pa1.w, h.w, l.w);
                *(uint4*)(sm + SA_HI + bsel + prow * 48 + phalf * 16) = h;
                *(uint4*)(sm + SA_LO + bsel + prow * 48 + phalf * 16) = l;
            }
            if (ks + 1 < 16) {
                const float4* ap = (const float4*)(Ab + (size_t)prow * 256 + (ks + 1) * 16 + phalf * 8);
                pa0 = ap[0]; pa1 = ap[1];
            }
            __syncthreads();

            uint32_t ah[2][4], al[2][4], bhr[2][4], blr[2][4];
#pragma unroll
            for (int mf = 0; mf < 2; ++mf) {
                uint32_t off = (uint32_t)((wm * 32 + mf * 16 + arow) * 48) + akh;
                ldsm4(ah[mf], sb + SA_HI + bsel + off);
                ldsm4(al[mf], sb + SA_LO + bsel + off);
            }
#pragma unroll
            for (int bp = 0; bp < 2; ++bp) {
                uint32_t off = (uint32_t)((wn * 32 + bp * 16 + bgat) * WSTRIDE)
                             + (uint32_t)((ks * 16 + bkh) * 2);
                ldsm4(bhr[bp], sb + SW_HI + off);
                ldsm4(blr[bp], sb + SW_LO + off);
            }
#pragma unroll
            for (int mf = 0; mf < 2; ++mf)
#pragma unroll
                for (int nf = 0; nf < 4; ++nf) {
                    const uint32_t* bh = &bhr[nf >> 1][(nf & 1) * 2];
                    const uint32_t* bl = &blr[nf >> 1][(nf & 1) * 2];
                    hmma(d[mf][nf], ah[mf], bh);
                    hmma(d[mf][nf], ah[mf], bl);
                    hmma(d[mf][nf], al[mf], bh);
                }
        }

        const float* bs = (const float*)(sm + SBIAS);
#pragma unroll
        for (int mf = 0; mf < 2; ++mf) {
            size_t row = (size_t)rt * 128 + wm * 32 + mf * 16 + grp;
#pragma unroll
            for (int nf = 0; nf < 4; ++nf) {
                int gc = wn * 32 + nf * 8 + 2 * tig;
                float bx = bs[gc], by = bs[gc + 1];
                float4 v = d[mf][nf];
                *(float2*)(C + row * 768 + g0 + gc)       = float2{v.x + bx, v.y + by};
                *(float2*)(C + (row + 8) * 768 + g0 + gc) = float2{v.z + bx, v.w + by};
            }
        }
    }
}

// ---------------- GRU recurrence v5: local-quarter-first k interleave ----------------
// Cluster of 4 CTAs owns 4 batch rows; CTA rank owns h columns [rank*64, +64).
// 512 threads = (c 0..63) x (k-eighth e 0..7). Thread computes ALL 3 gates x 4 rows
// x 32 k, where the 32 k are 8 from EACH quarter, processed in order
// rank, rank+1, rank+2, rank+3 (mod 4). The local quarter's h is available right
// after sync2 (no cluster round-trip), so every warp does ~1/4 of its FMA work
// BEFORE the single mbarrier wait -> the publish fence + DSMEM flight of the other
// CTAs is hidden under real FMA work instead of idle spinning.
// Publish mechanism unchanged from R10/R14 (sync2 -> tid0 fence + 4 arrives,
// single slot count=4 — the all-arrive backpressure keeps parity safe).
#define RSM_WN   0        // n-gate weights: [k4(64)][c(64)] float4 = 16384 floats
#define RSM_H    16384    // h double buffer: [2][4 rows][256] = 2048 floats
#define RSM_GH   18432    // gh partials: [e(8)][g(3)][r(4)][c(64)] = 6144 floats
#define RSM_MBAR 24576    // float offset of mbarrier (byte 98304, 8B aligned)
#define REC_SMEM (24576*4 + 64)

__global__ __launch_bounds__(512, 1) __cluster_dims__(4, 1, 1)
void gru_rec(const float* __restrict__ gx, const float* __restrict__ Whh,
             const float* __restrict__ bhh, float* __restrict__ out,
             float* __restrict__ hid)
{
    extern __shared__ float smem[];
    float4* sWn4 = (float4*)smem;       // n-gate weights [k4][c]
    float*  sH   = smem + RSM_H;        // double-buffered h
    float*  sGh  = smem + RSM_GH;       // gh partials
    const uint32_t mbarA = smem_u32(smem) + RSM_MBAR * 4;

    const uint32_t rank = cl_rank();
    const int b0  = (blockIdx.x >> 2) * 4;
    const int tid = threadIdx.x;
    const int e   = tid >> 6;          // k-eighth within each quarter (warp-pair uniform)
    const int c   = tid & 63;          // column within this CTA's 64-col chunk

    if (tid == 0) mbar_init(mbarA, 4);

    // n-gate weights -> SMEM [k4][c] float4 (k4 = k/4, 64 entries)
    for (int idx = tid; idx < 4096; idx += 512) {
        int k4 = idx >> 6, j = idx & 63;
        sWn4[idx] = ((const float4*)Whh)[(size_t)(512 + rank * 64 + j) * 64 + k4];
    }
    for (int i = tid; i < 2048; i += 512) sH[i] = 0.f;

    // r,z gate weights -> 64 registers, stored in QUARTER-VISIT ORDER:
    // visit qi: quarter q=(rank+qi)&3, k in [q*64 + e*8, +8) -> 4 u64 per quarter
    u64t wrR[16], wrZ[16];
#pragma unroll
    for (int qi = 0; qi < 4; ++qi) {
        const int q = ((int)rank + qi) & 3;
        const float* wbR = Whh + (size_t)(rank * 64 + c) * 256 + q * 64 + e * 8;
        const float* wbZ = wbR + 256 * 256;
#pragma unroll
        for (int kk = 0; kk < 2; ++kk) {
            ulonglong2 a = *(const ulonglong2*)(wbR + kk * 4);
            ulonglong2 b = *(const ulonglong2*)(wbZ + kk * 4);
            wrR[qi * 4 + 2 * kk] = a.x; wrR[qi * 4 + 2 * kk + 1] = a.y;
            wrZ[qi * 4 + 2 * kk] = b.x; wrZ[qi * 4 + 2 * kk + 1] = b.y;
        }
    }

    // epilogue mapping (tid < 256): one h element (erow, ecol)
    const int erow = (tid >> 6) & 3;
    const int ecol = tid & 63;
    float bR = 0.f, bZ = 0.f, bN = 0.f;
    if (tid < 256) {
        bR = bhh[rank * 64 + ecol];
        bZ = bhh[256 + rank * 64 + ecol];
        bN = bhh[512 + rank * 64 + ecol];
    }
    const size_t gxBase  = ((size_t)(b0 + erow) * 1024) * 768 + rank * 64 + ecol;
    const size_t outBase = ((size_t)(b0 + erow) * 1024) * 256 + rank * 64 + ecol;

    float gxr = 0.f, gxz = 0.f, gxn = 0.f;
    if (tid < 256) {
        gxr = gx[gxBase];
        gxz = gx[gxBase + 256];
        gxn = gx[gxBase + 512];
    }

    cl_sync();  // smem weights, zeroed h, mbarrier init visible cluster-wide

    for (int t = 0; t < 1024; ++t) {
        // ---- dot: 3 gates x 4 rows x 32 k, column c; local quarter FIRST ----
        {
            const float* hbuf = sH + (t & 1) * 1024;
            u64t aR[4], aZ[4], aN[4];
#pragma unroll
            for (int i = 0; i < 4; ++i) { aR[i] = 0ull; aZ[i] = 0ull; aN[i] = 0ull; }
#pragma unroll
            for (int qi = 0; qi < 4; ++qi) {
                // after the local quarter's FMAs, wait for the peers' h publish
                if (qi == 1 && t > 0)
                    mbar_wait_parity_cluster(mbarA, (uint32_t)((t - 1) & 1));
                const int q = ((int)rank + qi) & 3;
                const float*  hb = hbuf + q * 64 + e * 8;
                const float4* wn = sWn4 + (q * 16 + e * 2) * 64 + c;
#pragma unroll
                for (int kk = 0; kk < 2; ++kk) {
                    ulonglong2 wnv = *(const ulonglong2*)(wn + kk * 64);
                    u64t wr0 = wrR[qi * 4 + 2 * kk], wr1 = wrR[qi * 4 + 2 * kk + 1];
                    u64t wz0 = wrZ[qi * 4 + 2 * kk], wz1 = wrZ[qi * 4 + 2 * kk + 1];
#pragma unroll
                    for (int r = 0; r < 4; ++r) {
                        ulonglong2 hv = *(const ulonglong2*)(hb + r * 256 + kk * 4);
                        aR[r] = ffma2(wr0, hv.x, aR[r]);
                        aR[r] = ffma2(wr1, hv.y, aR[r]);
                        aZ[r] = ffma2(wz0, hv.x, aZ[r]);
                        aZ[r] = ffma2(wz1, hv.y, aZ[r]);
                        aN[r] = ffma2(wnv.x, hv.x, aN[r]);
                        aN[r] = ffma2(wnv.y, hv.y, aN[r]);
                    }
                }
            }
            float* sg = sGh + e * 768 + c;     // [e][g][r][c]
#pragma unroll
            for (int r = 0; r < 4; ++r) {
                float2 pr2 = unpack2(aR[r]);
                float2 pz2 = unpack2(aZ[r]);
                float2 pn2 = unpack2(aN[r]);
                sg[r * 64]        = pr2.x + pr2.y;
                sg[256 + r * 64]  = pz2.x + pz2.y;
                sg[512 + r * 64]  = pn2.x + pn2.y;
            }
        }
        __syncthreads();   // sGh complete before epilogue reads

        // ---- epilogue: warps 0..7, one element each ----
        float hnew = 0.f;
        if (tid < 256) {
            const int o = erow * 64 + ecol;
            float ghr = 0.f, ghz = 0.f, ghn = 0.f;
#pragma unroll
            for (int ee = 0; ee < 8; ++ee) {
                ghr += sGh[ee * 768 + o];
                ghz += sGh[ee * 768 + 256 + o];
                ghn += sGh[ee * 768 + 512 + o];
            }
            float r  = fast_sigmoid(gxr + ghr + bR);
            float z  = fast_sigmoid(gxz + ghz + bZ);
            float hp = sH[(t & 1) * 1024 + erow * 256 + rank * 64 + ecol];
            float n  = fast_tanh(fmaf(r, ghn + bN, gxn));
            hnew = fmaf(z, hp - n, n);   // (1-z)*n + z*hp

            float* hdst = sH + ((t + 1) & 1) * 1024 + erow * 256 + rank * 64 + ecol;
            *hdst = hnew;
            uint32_t laddr = smem_u32(hdst);
#pragma unroll
            for (int pr = 0; pr < 4; ++pr)
                if (pr != (int)rank) st_cl_f32(cl_map(laddr, (uint32_t)pr), hnew);
        }
        __syncthreads();  // all h stores issued before the signal; sGh reusable

        if (tid == 0) {
            asm volatile("fence.acq_rel.cluster;" ::: "memory");  // publish DSMEM writes
#pragma unroll
            for (int pr = 0; pr < 4; ++pr) mbar_arrive_cluster(mbarA, (uint32_t)pr);
        }
        // hidden under publish latency: out store + next-step gx prefetch
        if (tid < 256) {
            out[outBase + (size_t)t * 256] = hnew;
            if (t + 1 < 1024) {
                size_t gbase = gxBase + (size_t)(t + 1) * 768;
                gxr = gx[gbase];
                gxz = gx[gbase + 256];
                gxn = gx[gbase + 512];
            }
        }
    }

    if (tid < 256)
        hid[(size_t)(b0 + erow) * 256 + rank * 64 + ecol] =
            sH[erow * 256 + rank * 64 + ecol];   // final buffer = (1024 & 1) = 0
    cl_sync();  // no CTA exits while peers may still target its SMEM
}

// ---------------- launch ----------------
extern "C" void kernel_launch(void* const* d_in, const int* in_sizes, int n_in,
                              void* d_out, int out_size)
{
    const float* X      = (const float*)d_in[0];
    const float* w_ih_0 = (const float*)d_in[1];
    const float* w_hh_0 = (const float*)d_in[2];
    const float* b_ih_0 = (const float*)d_in[3];
    const float* b_hh_0 = (const float*)d_in[4];
    const float* w_ih_1 = (const float*)d_in[5];
    const float* w_hh_1 = (const float*)d_in[6];
    const float* b_ih_1 = (const float*)d_in[7];
    const float* b_hh_1 = (const float*)d_in[8];

    float* out1 = (float*)d_out;
    float* hid  = out1 + (size_t)ROWS * Mm;

    float *gx = nullptr, *o0 = nullptr;
    cudaGetSymbolAddress((void**)&gx, g_gx);
    cudaGetSymbolAddress((void**)&o0, g_out0);

    cudaFuncSetAttribute(gru_rec, cudaFuncAttributeMaxDynamicSharedMemorySize, REC_SMEM);
    cudaFuncSetAttribute(gemm_hmma, cudaFuncAttributeMaxDynamicSharedMemorySize, SM_GEMM);

    dim3 ggrid(12, 24);   // 12 gate-tiles x 24 row-streams

    // layer 0
    gemm_hmma<<<ggrid, 256, SM_GEMM>>>(X, w_ih_0, b_ih_0, gx);
    gru_rec<<<128, 512, REC_SMEM>>>(gx, w_hh_0, b_hh_0, o0, hid);
    // layer 1
    gemm_hmma<<<ggrid, 256, SM_GEMM>>>(o0, w_ih_1, b_ih_1, gx);
    gru_rec<<<128, 512, REC_SMEM>>>(gx, w_hh_1, b_hh_1, out1, hid + (size_t)Bb * Mm);
}